// round 5
// baseline (speedup 1.0000x reference)
#include <cuda_runtime.h>
#include <cstdint>

// Problem dims (fixed by reference)
#define NB   32
#define H0   512
#define W0   512
#define H1   256
#define W1   256
#define H2   128
#define W2   128
#define MPIX (H2*W2)   // 16384
#define K3_CHUNKS 8

// Scratch (device globals: allocation-free)
__device__ float g_h1[(size_t)NB * H1 * W1 * 4];   // NHWC (4ch per pixel)
__device__ float g_h2[(size_t)NB * MPIX * 16];     // NHWC pixel-major
__device__ float g_part[NB][K3_CHUNKS][68];        // netvlad partials
__device__ int   g_done[NB];                        // zero-init; self-resetting

// ---------------------------------------------------------------------------
// tf32 helpers
// ---------------------------------------------------------------------------
__device__ __forceinline__ uint32_t cvt_tf32(float v) {
    uint32_t r; asm("cvt.rna.tf32.f32 %0,%1;" : "=r"(r) : "f"(v)); return r;
}
__device__ __forceinline__ void mma8(float c[4],
    uint32_t a0, uint32_t a1, uint32_t a2, uint32_t a3,
    uint32_t b0, uint32_t b1)
{
    asm volatile(
        "mma.sync.aligned.m16n8k8.row.col.f32.tf32.tf32.f32 "
        "{%0,%1,%2,%3},{%4,%5,%6,%7},{%8,%9},{%0,%1,%2,%3};"
        : "+f"(c[0]), "+f"(c[1]), "+f"(c[2]), "+f"(c[3])
        : "r"(a0), "r"(a1), "r"(a2), "r"(a3), "r"(b0), "r"(b1));
}

// ---------------------------------------------------------------------------
// Kernel 1: conv1(3->4, 3x3 SAME) + ReLU + 2x2 avgpool, NCHW -> NHWC (scalar)
// grid = (H1, NB), block = 256
// ---------------------------------------------------------------------------
__global__ void __launch_bounds__(W1) conv1_pool_kernel(
    const float* __restrict__ x,
    const float* __restrict__ w,   // (4,3,3,3)
    const float* __restrict__ b)
{
    __shared__ float4 sw4[27];
    __shared__ float  sb[4];
    const int tid = threadIdx.x;
    if (tid < 27)
        sw4[tid] = make_float4(w[tid], w[27 + tid], w[54 + tid], w[81 + tid]);
    if (tid < 4) sb[tid] = b[tid];
    __syncthreads();

    const int px = tid;
    const int py = blockIdx.x;
    const int n  = blockIdx.y;
    const int y0 = 2 * py - 1;
    const int x0 = 2 * px - 1;

    float p[3][4][4];
    const bool interior = (px >= 1) & (px <= 254) & (py >= 1) & (py <= 254);
    if (interior) {
        const float* bp = x + (size_t)n * 3 * H0 * W0 + (size_t)y0 * W0 + x0;
#pragma unroll
        for (int c = 0; c < 3; ++c)
#pragma unroll
            for (int dy = 0; dy < 4; ++dy)
#pragma unroll
                for (int dx = 0; dx < 4; ++dx)
                    p[c][dy][dx] = __ldg(bp + c * (H0 * W0) + dy * W0 + dx);
    } else {
        const float* xn = x + (size_t)n * 3 * H0 * W0;
#pragma unroll
        for (int c = 0; c < 3; ++c) {
            const float* xc = xn + (size_t)c * H0 * W0;
#pragma unroll
            for (int dy = 0; dy < 4; ++dy) {
                const int y = y0 + dy;
                const bool yok = ((unsigned)y < (unsigned)H0);
#pragma unroll
                for (int dx = 0; dx < 4; ++dx) {
                    const int xx = x0 + dx;
                    p[c][dy][dx] = (yok && (unsigned)xx < (unsigned)W0)
                                       ? __ldg(xc + (size_t)y * W0 + xx) : 0.0f;
                }
            }
        }
    }

    float a00[4], a01[4], a10[4], a11[4];
#pragma unroll
    for (int co = 0; co < 4; ++co) {
        const float bb = sb[co];
        a00[co] = bb; a01[co] = bb; a10[co] = bb; a11[co] = bb;
    }
#pragma unroll
    for (int c = 0; c < 3; ++c)
#pragma unroll
        for (int ky = 0; ky < 3; ++ky)
#pragma unroll
            for (int kx = 0; kx < 3; ++kx) {
                const float4 w4 = sw4[c * 9 + ky * 3 + kx];
                const float t00 = p[c][ky    ][kx    ];
                const float t01 = p[c][ky    ][kx + 1];
                const float t10 = p[c][ky + 1][kx    ];
                const float t11 = p[c][ky + 1][kx + 1];
                a00[0] = fmaf(t00, w4.x, a00[0]); a00[1] = fmaf(t00, w4.y, a00[1]);
                a00[2] = fmaf(t00, w4.z, a00[2]); a00[3] = fmaf(t00, w4.w, a00[3]);
                a01[0] = fmaf(t01, w4.x, a01[0]); a01[1] = fmaf(t01, w4.y, a01[1]);
                a01[2] = fmaf(t01, w4.z, a01[2]); a01[3] = fmaf(t01, w4.w, a01[3]);
                a10[0] = fmaf(t10, w4.x, a10[0]); a10[1] = fmaf(t10, w4.y, a10[1]);
                a10[2] = fmaf(t10, w4.z, a10[2]); a10[3] = fmaf(t10, w4.w, a10[3]);
                a11[0] = fmaf(t11, w4.x, a11[0]); a11[1] = fmaf(t11, w4.y, a11[1]);
                a11[2] = fmaf(t11, w4.z, a11[2]); a11[3] = fmaf(t11, w4.w, a11[3]);
            }

    float res[4];
#pragma unroll
    for (int co = 0; co < 4; ++co)
        res[co] = 0.25f * (fmaxf(a00[co], 0.f) + fmaxf(a01[co], 0.f) +
                           fmaxf(a10[co], 0.f) + fmaxf(a11[co], 0.f));
    float4* o = (float4*)(g_h1 + (((size_t)n * H1 + py) * W1 + px) * 4);
    *o = make_float4(res[0], res[1], res[2], res[3]);
}

// ---------------------------------------------------------------------------
// Kernel 2: conv2 as implicit GEMM on tensor cores (3xTF32), + ReLU + pool.
// Block = 128 threads (4 warps). Block computes pooled row py of image n.
// Warp w: conv row 2*py + (w&1), col half (w>>1)*128 .. +128 (8 m16 tiles).
// K ordering: k = cell*4 + ci, cell = ky*3+kx (0..8), K padded to 40.
// grid = (H2, NB)
// ---------------------------------------------------------------------------
__global__ void __launch_bounds__(128) conv2_tc_kernel(
    const float* __restrict__ wgt,   // (16,4,3,3): w[co*36 + ci*9 + cell]
    const float* __restrict__ bias)
{
    __shared__ float s[2][256][17];   // [conv row parity][x][co], pad 17
    __shared__ float sb[16];
    const int tid  = threadIdx.x;
    const int wid  = tid >> 5;
    const int lane = tid & 31;
    const int qr   = lane >> 2;   // t/4
    const int qc   = lane & 3;    // t%4
    const int py = blockIdx.x;
    const int n  = blockIdx.y;
    if (tid < 16) sb[tid] = bias[tid];

    // B fragments: Bmat[k][co] = wgt[co*36 + (k%4)*9 + k/4], k<36 else 0.
    // b0: k = 8c+qc (cell 2c, ci=qc); b1: k = 8c+qc+4 (cell 2c+1, ci=qc)
    uint32_t Bh[2][5][2], Bl[2][5][2];
#pragma unroll
    for (int nt = 0; nt < 2; ++nt) {
        const int co = nt * 8 + qr;
#pragma unroll
        for (int c = 0; c < 5; ++c)
#pragma unroll
            for (int j = 0; j < 2; ++j) {
                const int cell = 2 * c + j;
                const float v = (cell < 9) ? __ldg(wgt + co * 36 + qc * 9 + cell) : 0.0f;
                const uint32_t h = cvt_tf32(v);
                Bh[nt][c][j] = h;
                Bl[nt][c][j] = cvt_tf32(v - __uint_as_float(h));
            }
    }
    __syncthreads();

    const int r  = 2 * py + (wid & 1);   // conv row of this warp
    const int ch = wid >> 1;             // column half
    const float* hrow = g_h1 + (size_t)n * H1 * W1 * 4;

#pragma unroll 1
    for (int mt = 0; mt < 8; ++mt) {
        const int x0 = ch * 128 + mt * 16;
        const int xa = x0 + qr;
        const int xb = xa + 8;

        // load the 9 taps for both m-rows (cell = ky*3+kx), ci = qc
        float va[9], vb[9];
#pragma unroll
        for (int cell = 0; cell < 9; ++cell) {
            const int ky = cell / 3, kx = cell % 3;
            const int ry = r + ky - 1;
            const bool yok = ((unsigned)ry < (unsigned)H1);
            const int ca = xa + kx - 1;
            const int cb = xb + kx - 1;
            va[cell] = (yok && (unsigned)ca < (unsigned)W1)
                           ? __ldg(hrow + ((size_t)ry * W1 + ca) * 4 + qc) : 0.0f;
            vb[cell] = (yok && (unsigned)cb < (unsigned)W1)
                           ? __ldg(hrow + ((size_t)ry * W1 + cb) * 4 + qc) : 0.0f;
        }
        uint32_t Ah[9], Al[9], Ch_[9], Cl_[9];  // hi/lo for va (rows 0-7) and vb (rows 8-15)
#pragma unroll
        for (int cell = 0; cell < 9; ++cell) {
            uint32_t h = cvt_tf32(va[cell]);
            Ah[cell] = h; Al[cell] = cvt_tf32(va[cell] - __uint_as_float(h));
            h = cvt_tf32(vb[cell]);
            Ch_[cell] = h; Cl_[cell] = cvt_tf32(vb[cell] - __uint_as_float(h));
        }

        float C0[4] = {0.f, 0.f, 0.f, 0.f};
        float C1[4] = {0.f, 0.f, 0.f, 0.f};
#pragma unroll
        for (int c = 0; c < 5; ++c) {
            const int e0 = 2 * c, e1 = 2 * c + 1;
            const uint32_t a0h = Ah[e0],  a1h = Ch_[e0];
            const uint32_t a2h = (e1 < 9) ? Ah[e1]  : 0u;
            const uint32_t a3h = (e1 < 9) ? Ch_[e1] : 0u;
            const uint32_t a0l = Al[e0],  a1l = Cl_[e0];
            const uint32_t a2l = (e1 < 9) ? Al[e1]  : 0u;
            const uint32_t a3l = (e1 < 9) ? Cl_[e1] : 0u;
            // 3xTF32: hi*hi + lo*hi + hi*lo
            mma8(C0, a0h, a1h, a2h, a3h, Bh[0][c][0], Bh[0][c][1]);
            mma8(C0, a0l, a1l, a2l, a3l, Bh[0][c][0], Bh[0][c][1]);
            mma8(C0, a0h, a1h, a2h, a3h, Bl[0][c][0], Bl[0][c][1]);
            mma8(C1, a0h, a1h, a2h, a3h, Bh[1][c][0], Bh[1][c][1]);
            mma8(C1, a0l, a1l, a2l, a3l, Bh[1][c][0], Bh[1][c][1]);
            mma8(C1, a0h, a1h, a2h, a3h, Bl[1][c][0], Bl[1][c][1]);
        }

        // epilogue: bias + relu -> smem. C[m][nn]: c0=(qr,2qc) c1=+1col c2/c3 rows+8
        const int rp = wid & 1;
#pragma unroll
        for (int nt = 0; nt < 2; ++nt) {
            const float* C = nt ? C1 : C0;
            const int co = nt * 8 + 2 * qc;
            s[rp][x0 + qr    ][co    ] = fmaxf(C[0] + sb[co    ], 0.f);
            s[rp][x0 + qr    ][co + 1] = fmaxf(C[1] + sb[co + 1], 0.f);
            s[rp][x0 + qr + 8][co    ] = fmaxf(C[2] + sb[co    ], 0.f);
            s[rp][x0 + qr + 8][co + 1] = fmaxf(C[3] + sb[co + 1], 0.f);
        }
    }
    __syncthreads();

    // 2x2 avg pool -> g_h2 (pixel-major NHWC16)
    const int px = tid;   // 0..127
    float* o = g_h2 + ((size_t)n * MPIX + (size_t)py * W2 + px) * 16;
    float4* o4 = (float4*)o;
#pragma unroll
    for (int q = 0; q < 4; ++q) {
        float v[4];
#pragma unroll
        for (int j = 0; j < 4; ++j) {
            const int co = q * 4 + j;
            v[j] = 0.25f * (s[0][2 * px][co] + s[0][2 * px + 1][co] +
                            s[1][2 * px][co] + s[1][2 * px + 1][co]);
        }
        o4[q] = make_float4(v[0], v[1], v[2], v[3]);
    }
}

// ---------------------------------------------------------------------------
// Kernel 3: NetVLAD partials + last-block finalize. grid=(NB, K3_CHUNKS), 256t
// ---------------------------------------------------------------------------
#define K3A_THREADS 256
__global__ void __launch_bounds__(K3A_THREADS) netvlad_fused_kernel(
    const float* __restrict__ aw, const float* __restrict__ ab,
    const float* __restrict__ cent,
    const float* __restrict__ lw, const float* __restrict__ lb,
    float* __restrict__ out)
{
    const int n   = blockIdx.x;
    const int ch  = blockIdx.y;
    const int tid = threadIdx.x;
    const int lane = tid & 31;
    const int wrp  = tid >> 5;

    __shared__ float s_aw[64];
    __shared__ float s_ab[4];
    if (tid < 64) s_aw[tid] = aw[tid];
    if (tid < 4)  s_ab[tid] = ab[tid];
    __syncthreads();

    float acc[68];
#pragma unroll
    for (int i = 0; i < 68; ++i) acc[i] = 0.0f;

    const int m0 = ch * (MPIX / K3_CHUNKS);
    const int m1 = m0 + (MPIX / K3_CHUNKS);
    const float* base = g_h2 + (size_t)n * MPIX * 16;
    for (int m = m0 + tid; m < m1; m += K3A_THREADS) {
        const float4* xp = (const float4*)(base + (size_t)m * 16);
        float xv[16];
#pragma unroll
        for (int q = 0; q < 4; ++q) {
            float4 v = xp[q];
            xv[q*4+0] = v.x; xv[q*4+1] = v.y; xv[q*4+2] = v.z; xv[q*4+3] = v.w;
        }
        float lg[4];
#pragma unroll
        for (int k = 0; k < 4; ++k) {
            float sres = s_ab[k];
#pragma unroll
            for (int c = 0; c < 16; ++c) sres = fmaf(xv[c], s_aw[k * 16 + c], sres);
            lg[k] = sres;
        }
        const float mx = fmaxf(fmaxf(lg[0], lg[1]), fmaxf(lg[2], lg[3]));
        float e[4], es = 0.0f;
#pragma unroll
        for (int k = 0; k < 4; ++k) { e[k] = __expf(lg[k] - mx); es += e[k]; }
        const float inv = __fdividef(1.0f, es);
#pragma unroll
        for (int k = 0; k < 4; ++k) {
            const float a = e[k] * inv;
            acc[64 + k] += a;
#pragma unroll
            for (int c = 0; c < 16; ++c)
                acc[k * 16 + c] = fmaf(a, xv[c], acc[k * 16 + c]);
        }
    }

#pragma unroll
    for (int off = 16; off > 0; off >>= 1)
#pragma unroll
        for (int i = 0; i < 68; ++i)
            acc[i] += __shfl_down_sync(0xffffffffu, acc[i], off);

    __shared__ float red[K3A_THREADS / 32][68];
    if (lane == 0)
#pragma unroll
        for (int i = 0; i < 68; ++i) red[wrp][i] = acc[i];
    __syncthreads();
    if (tid < 68) {
        float sres = 0.0f;
#pragma unroll
        for (int ww = 0; ww < K3A_THREADS / 32; ++ww) sres += red[ww][tid];
        g_part[n][ch][tid] = sres;
    }

    // ---- last-block-per-image finalize ----
    __threadfence();
    __shared__ int s_last;
    if (tid == 0) {
        const int old = atomicAdd(&g_done[n], 1);
        s_last = (old == K3_CHUNKS - 1) ? 1 : 0;
    }
    __syncthreads();
    if (!s_last) return;

    __shared__ float sv[68];
    if (tid < 68) {
        float sres = 0.0f;
#pragma unroll
        for (int cc = 0; cc < K3_CHUNKS; ++cc) sres += __ldcg(&g_part[n][cc][tid]);
        sv[tid] = sres;
    }
    __syncthreads();

    __shared__ float v2[64];
    __shared__ float nk[4];
    __shared__ float gn;
    if (tid < 64) {
        const int k = tid >> 4;
        v2[tid] = sv[tid] - sv[64 + k] * __ldg(cent + tid);
    }
    __syncthreads();
    if (tid < 4) {
        float sres = 0.0f;
#pragma unroll
        for (int c = 0; c < 16; ++c) { const float v = v2[tid * 16 + c]; sres = fmaf(v, v, sres); }
        nk[tid] = fmaxf(sqrtf(sres), 1e-12f);
    }
    __syncthreads();
    if (tid < 64) v2[tid] = v2[tid] / nk[tid >> 4];
    __syncthreads();
    if (tid == 0) {
        float sres = 0.0f;
#pragma unroll
        for (int i = 0; i < 64; ++i) sres = fmaf(v2[i], v2[i], sres);
        gn = fmaxf(sqrtf(sres), 1e-12f);
        g_done[n] = 0;   // reset for next graph replay
    }
    __syncthreads();
    if (tid < 7) {
        float sres = __ldg(lb + tid);
        const float ig = 1.0f / gn;
#pragma unroll
        for (int i = 0; i < 64; ++i)
            sres = fmaf(v2[i] * ig, __ldg(lw + tid * 64 + i), sres);
        out[n * 7 + tid] = sres;
    }
}

// ---------------------------------------------------------------------------
extern "C" void kernel_launch(void* const* d_in, const int* in_sizes, int n_in,
                              void* d_out, int out_size)
{
    (void)in_sizes; (void)n_in; (void)out_size;
    const float* x       = (const float*)d_in[0];
    const float* conv1_w = (const float*)d_in[1];
    const float* conv1_b = (const float*)d_in[2];
    const float* conv2_w = (const float*)d_in[3];
    const float* conv2_b = (const float*)d_in[4];
    const float* cent    = (const float*)d_in[5];
    const float* aw      = (const float*)d_in[6];
    const float* ab      = (const float*)d_in[7];
    const float* lw      = (const float*)d_in[8];
    const float* lb      = (const float*)d_in[9];
    float* out = (float*)d_out;

    dim3 g1(H1, NB); conv1_pool_kernel<<<g1, W1>>>(x, conv1_w, conv1_b);
    dim3 g2(H2, NB); conv2_tc_kernel<<<g2, 128>>>(conv2_w, conv2_b);
    dim3 g3(NB, K3_CHUNKS);
    netvlad_fused_kernel<<<g3, K3A_THREADS>>>(aw, ab, cent, lw, lb, out);
}

// round 7
// speedup vs baseline: 1.2024x; 1.2024x over previous
#include <cuda_runtime.h>
#include <cstdint>

// Problem dims (fixed by reference)
#define NB   32
#define H0   512
#define W0   512
#define H1   256
#define W1   256
#define H2   128
#define W2   128
#define MPIX (H2*W2)   // 16384
#define K3_CHUNKS 8

// Scratch (device globals: allocation-free)
__device__ float g_h1[(size_t)NB * H1 * W1 * 4];   // NHWC (4ch per pixel)
__device__ float g_h2[(size_t)NB * MPIX * 16];     // NHWC pixel-major
__device__ float g_part[NB][K3_CHUNKS][68];        // netvlad partials
__device__ int   g_done[NB];                        // zero-init; self-resetting

// ---------------------------------------------------------------------------
// Kernel 1: conv1(3->4, 3x3 SAME) + ReLU + 2x2 avgpool, NCHW -> NHWC.
// Smem-staged: block = one pooled row; stage 4 input rows x 512 x 3ch.
// grid = (H1, NB), block = 256
// ---------------------------------------------------------------------------
__global__ void __launch_bounds__(W1) conv1_pool_kernel(
    const float* __restrict__ x,
    const float* __restrict__ w,   // (4,3,3,3)
    const float* __restrict__ b)
{
    __shared__ float  s_in[3][4][516];   // [ci][row][1+col], halo cols 0 & 513 = 0
    __shared__ float4 sw4[27];
    __shared__ float  sb[4];
    const int tid = threadIdx.x;
    if (tid < 27)
        sw4[tid] = make_float4(w[tid], w[27 + tid], w[54 + tid], w[81 + tid]);
    if (tid < 4) sb[tid] = b[tid];

    const int py = blockIdx.x;
    const int n  = blockIdx.y;
    const int y0 = 2 * py - 1;

    if (tid < 12) {
        const int c = tid >> 2, r = tid & 3;
        s_in[c][r][0]   = 0.0f;
        s_in[c][r][513] = 0.0f;
    }

    // cooperative staging: 3*4*512 = 6144 scalars, 24 per thread, coalesced
    const float* xn = x + (size_t)n * 3 * H0 * W0;
#pragma unroll
    for (int i = 0; i < 24; ++i) {
        const int idx = tid + i * 256;       // c*2048 + r*512 + col
        const int col = idx & 511;
        const int r   = (idx >> 9) & 3;
        const int c   = idx >> 11;
        const int y   = y0 + r;
        const float v = ((unsigned)y < (unsigned)H0)
                            ? __ldg(xn + (size_t)c * H0 * W0 + (size_t)y * W0 + col)
                            : 0.0f;
        s_in[c][r][1 + col] = v;
    }
    __syncthreads();

    const int px = tid;
    float a00[4], a01[4], a10[4], a11[4];
#pragma unroll
    for (int co = 0; co < 4; ++co) {
        const float bb = sb[co];
        a00[co] = bb; a01[co] = bb; a10[co] = bb; a11[co] = bb;
    }

#pragma unroll
    for (int c = 0; c < 3; ++c) {
        float p[4][4];
#pragma unroll
        for (int dy = 0; dy < 4; ++dy)
#pragma unroll
            for (int dx = 0; dx < 4; ++dx)
                p[dy][dx] = s_in[c][dy][2 * px + dx];   // conv col (2px-1)+dx
#pragma unroll
        for (int ky = 0; ky < 3; ++ky)
#pragma unroll
            for (int kx = 0; kx < 3; ++kx) {
                const float4 w4 = sw4[c * 9 + ky * 3 + kx];
                const float t00 = p[ky    ][kx    ];
                const float t01 = p[ky    ][kx + 1];
                const float t10 = p[ky + 1][kx    ];
                const float t11 = p[ky + 1][kx + 1];
                a00[0] = fmaf(t00, w4.x, a00[0]); a00[1] = fmaf(t00, w4.y, a00[1]);
                a00[2] = fmaf(t00, w4.z, a00[2]); a00[3] = fmaf(t00, w4.w, a00[3]);
                a01[0] = fmaf(t01, w4.x, a01[0]); a01[1] = fmaf(t01, w4.y, a01[1]);
                a01[2] = fmaf(t01, w4.z, a01[2]); a01[3] = fmaf(t01, w4.w, a01[3]);
                a10[0] = fmaf(t10, w4.x, a10[0]); a10[1] = fmaf(t10, w4.y, a10[1]);
                a10[2] = fmaf(t10, w4.z, a10[2]); a10[3] = fmaf(t10, w4.w, a10[3]);
                a11[0] = fmaf(t11, w4.x, a11[0]); a11[1] = fmaf(t11, w4.y, a11[1]);
                a11[2] = fmaf(t11, w4.z, a11[2]); a11[3] = fmaf(t11, w4.w, a11[3]);
            }
    }

    float res[4];
#pragma unroll
    for (int co = 0; co < 4; ++co)
        res[co] = 0.25f * (fmaxf(a00[co], 0.f) + fmaxf(a01[co], 0.f) +
                           fmaxf(a10[co], 0.f) + fmaxf(a11[co], 0.f));
    float4* o = (float4*)(g_h1 + (((size_t)n * H1 + py) * W1 + px) * 4);
    *o = make_float4(res[0], res[1], res[2], res[3]);
}

// ---------------------------------------------------------------------------
// Kernel 2: conv2(4->16, 3x3 SAME) + ReLU + 2x2 avgpool, NHWC -> NHWC (scalar,
// proven R3 version). grid = (H2, NB), block = 128
// ---------------------------------------------------------------------------
__global__ void __launch_bounds__(W2) conv2_pool_kernel(
    const float* __restrict__ w,   // (16,4,3,3)
    const float* __restrict__ b)
{
    __shared__ float4 sw4[4][36];
    __shared__ float  sb[16];
    const int tid = threadIdx.x;
    for (int i = tid; i < 144; i += W2) {
        const int g = i / 36, idx = i % 36;
        sw4[g][idx] = make_float4(w[(g * 4 + 0) * 36 + idx], w[(g * 4 + 1) * 36 + idx],
                                  w[(g * 4 + 2) * 36 + idx], w[(g * 4 + 3) * 36 + idx]);
    }
    if (tid < 16) sb[tid] = b[tid];
    __syncthreads();

    const int px = tid;
    const int py = blockIdx.x;
    const int n  = blockIdx.y;
    const int y0 = 2 * py - 1;
    const int x0 = 2 * px - 1;

    float p[4][4][4];
    const bool interior = (px >= 1) & (px <= 126) & (py >= 1) & (py <= 126);
    if (interior) {
        const float* bp = g_h1 + ((size_t)n * H1 * W1 + (size_t)y0 * W1 + x0) * 4;
#pragma unroll
        for (int dy = 0; dy < 4; ++dy)
#pragma unroll
            for (int dx = 0; dx < 4; ++dx) {
                const float4 t = *(const float4*)(bp + (dy * W1 + dx) * 4);
                p[dy][dx][0] = t.x; p[dy][dx][1] = t.y;
                p[dy][dx][2] = t.z; p[dy][dx][3] = t.w;
            }
    } else {
        const float* hn = g_h1 + (size_t)n * H1 * W1 * 4;
#pragma unroll
        for (int dy = 0; dy < 4; ++dy) {
            const int y = y0 + dy;
            const bool yok = ((unsigned)y < (unsigned)H1);
#pragma unroll
            for (int dx = 0; dx < 4; ++dx) {
                const int xx = x0 + dx;
                float4 t = make_float4(0.f, 0.f, 0.f, 0.f);
                if (yok && (unsigned)xx < (unsigned)W1)
                    t = *(const float4*)(hn + ((size_t)y * W1 + xx) * 4);
                p[dy][dx][0] = t.x; p[dy][dx][1] = t.y;
                p[dy][dx][2] = t.z; p[dy][dx][3] = t.w;
            }
        }
    }

    float res[16];
#pragma unroll
    for (int g = 0; g < 4; ++g) {
        float a00[4], a01[4], a10[4], a11[4];
#pragma unroll
        for (int j = 0; j < 4; ++j) {
            const float bb = sb[g * 4 + j];
            a00[j] = bb; a01[j] = bb; a10[j] = bb; a11[j] = bb;
        }
#pragma unroll
        for (int ci = 0; ci < 4; ++ci)
#pragma unroll
            for (int ky = 0; ky < 3; ++ky)
#pragma unroll
                for (int kx = 0; kx < 3; ++kx) {
                    const float4 w4 = sw4[g][(ci * 3 + ky) * 3 + kx];
                    const float t00 = p[ky    ][kx    ][ci];
                    const float t01 = p[ky    ][kx + 1][ci];
                    const float t10 = p[ky + 1][kx    ][ci];
                    const float t11 = p[ky + 1][kx + 1][ci];
                    a00[0] = fmaf(t00, w4.x, a00[0]); a00[1] = fmaf(t00, w4.y, a00[1]);
                    a00[2] = fmaf(t00, w4.z, a00[2]); a00[3] = fmaf(t00, w4.w, a00[3]);
                    a01[0] = fmaf(t01, w4.x, a01[0]); a01[1] = fmaf(t01, w4.y, a01[1]);
                    a01[2] = fmaf(t01, w4.z, a01[2]); a01[3] = fmaf(t01, w4.w, a01[3]);
                    a10[0] = fmaf(t10, w4.x, a10[0]); a10[1] = fmaf(t10, w4.y, a10[1]);
                    a10[2] = fmaf(t10, w4.z, a10[2]); a10[3] = fmaf(t10, w4.w, a10[3]);
                    a11[0] = fmaf(t11, w4.x, a11[0]); a11[1] = fmaf(t11, w4.y, a11[1]);
                    a11[2] = fmaf(t11, w4.z, a11[2]); a11[3] = fmaf(t11, w4.w, a11[3]);
                }
#pragma unroll
        for (int j = 0; j < 4; ++j)
            res[g * 4 + j] = 0.25f * (fmaxf(a00[j], 0.f) + fmaxf(a01[j], 0.f) +
                                      fmaxf(a10[j], 0.f) + fmaxf(a11[j], 0.f));
    }

    float4* o4 = (float4*)(g_h2 + ((size_t)n * MPIX + (size_t)py * W2 + px) * 16);
#pragma unroll
    for (int q = 0; q < 4; ++q)
        o4[q] = make_float4(res[q*4+0], res[q*4+1], res[q*4+2], res[q*4+3]);
}

// ---------------------------------------------------------------------------
// Kernel 3: NetVLAD partials + last-block finalize. grid=(NB, K3_CHUNKS), 256t
// ---------------------------------------------------------------------------
#define K3A_THREADS 256
__global__ void __launch_bounds__(K3A_THREADS) netvlad_fused_kernel(
    const float* __restrict__ aw, const float* __restrict__ ab,
    const float* __restrict__ cent,
    const float* __restrict__ lw, const float* __restrict__ lb,
    float* __restrict__ out)
{
    const int n   = blockIdx.x;
    const int ch  = blockIdx.y;
    const int tid = threadIdx.x;
    const int lane = tid & 31;
    const int wrp  = tid >> 5;

    __shared__ float s_aw[64];
    __shared__ float s_ab[4];
    if (tid < 64) s_aw[tid] = aw[tid];
    if (tid < 4)  s_ab[tid] = ab[tid];
    __syncthreads();

    float acc[68];
#pragma unroll
    for (int i = 0; i < 68; ++i) acc[i] = 0.0f;

    const int m0 = ch * (MPIX / K3_CHUNKS);
    const int m1 = m0 + (MPIX / K3_CHUNKS);
    const float* base = g_h2 + (size_t)n * MPIX * 16;
    for (int m = m0 + tid; m < m1; m += K3A_THREADS) {
        const float4* xp = (const float4*)(base + (size_t)m * 16);
        float xv[16];
#pragma unroll
        for (int q = 0; q < 4; ++q) {
            float4 v = xp[q];
            xv[q*4+0] = v.x; xv[q*4+1] = v.y; xv[q*4+2] = v.z; xv[q*4+3] = v.w;
        }
        float lg[4];
#pragma unroll
        for (int k = 0; k < 4; ++k) {
            float sres = s_ab[k];
#pragma unroll
            for (int c = 0; c < 16; ++c) sres = fmaf(xv[c], s_aw[k * 16 + c], sres);
            lg[k] = sres;
        }
        const float mx = fmaxf(fmaxf(lg[0], lg[1]), fmaxf(lg[2], lg[3]));
        float e[4], es = 0.0f;
#pragma unroll
        for (int k = 0; k < 4; ++k) { e[k] = __expf(lg[k] - mx); es += e[k]; }
        const float inv = __fdividef(1.0f, es);
#pragma unroll
        for (int k = 0; k < 4; ++k) {
            const float a = e[k] * inv;
            acc[64 + k] += a;
#pragma unroll
            for (int c = 0; c < 16; ++c)
                acc[k * 16 + c] = fmaf(a, xv[c], acc[k * 16 + c]);
        }
    }

#pragma unroll
    for (int off = 16; off > 0; off >>= 1)
#pragma unroll
        for (int i = 0; i < 68; ++i)
            acc[i] += __shfl_down_sync(0xffffffffu, acc[i], off);

    __shared__ float red[K3A_THREADS / 32][68];
    if (lane == 0)
#pragma unroll
        for (int i = 0; i < 68; ++i) red[wrp][i] = acc[i];
    __syncthreads();
    if (tid < 68) {
        float sres = 0.0f;
#pragma unroll
        for (int ww = 0; ww < K3A_THREADS / 32; ++ww) sres += red[ww][tid];
        g_part[n][ch][tid] = sres;
    }

    // ---- last-block-per-image finalize ----
    __threadfence();
    __shared__ int s_last;
    if (tid == 0) {
        const int old = atomicAdd(&g_done[n], 1);
        s_last = (old == K3_CHUNKS - 1) ? 1 : 0;
    }
    __syncthreads();
    if (!s_last) return;

    __shared__ float sv[68];
    if (tid < 68) {
        float sres = 0.0f;
#pragma unroll
        for (int cc = 0; cc < K3_CHUNKS; ++cc) sres += __ldcg(&g_part[n][cc][tid]);
        sv[tid] = sres;
    }
    __syncthreads();

    __shared__ float v2[64];
    __shared__ float nk[4];
    __shared__ float gn;
    if (tid < 64) {
        const int k = tid >> 4;
        v2[tid] = sv[tid] - sv[64 + k] * __ldg(cent + tid);
    }
    __syncthreads();
    if (tid < 4) {
        float sres = 0.0f;
#pragma unroll
        for (int c = 0; c < 16; ++c) { const float v = v2[tid * 16 + c]; sres = fmaf(v, v, sres); }
        nk[tid] = fmaxf(sqrtf(sres), 1e-12f);
    }
    __syncthreads();
    if (tid < 64) v2[tid] = v2[tid] / nk[tid >> 4];
    __syncthreads();
    if (tid == 0) {
        float sres = 0.0f;
#pragma unroll
        for (int i = 0; i < 64; ++i) sres = fmaf(v2[i], v2[i], sres);
        gn = fmaxf(sqrtf(sres), 1e-12f);
        g_done[n] = 0;   // reset for next graph replay
    }
    __syncthreads();
    if (tid < 7) {
        float sres = __ldg(lb + tid);
        const float ig = 1.0f / gn;
#pragma unroll
        for (int i = 0; i < 64; ++i)
            sres = fmaf(v2[i] * ig, __ldg(lw + tid * 64 + i), sres);
        out[n * 7 + tid] = sres;
    }
}

// ---------------------------------------------------------------------------
extern "C" void kernel_launch(void* const* d_in, const int* in_sizes, int n_in,
                              void* d_out, int out_size)
{
    (void)in_sizes; (void)n_in; (void)out_size;
    const float* x       = (const float*)d_in[0];
    const float* conv1_w = (const float*)d_in[1];
    const float* conv1_b = (const float*)d_in[2];
    const float* conv2_w = (const float*)d_in[3];
    const float* conv2_b = (const float*)d_in[4];
    const float* cent    = (const float*)d_in[5];
    const float* aw      = (const float*)d_in[6];
    const float* ab      = (const float*)d_in[7];
    const float* lw      = (const float*)d_in[8];
    const float* lb      = (const float*)d_in[9];
    float* out = (float*)d_out;

    dim3 g1(H1, NB); conv1_pool_kernel<<<g1, W1>>>(x, conv1_w, conv1_b);
    dim3 g2(H2, NB); conv2_pool_kernel<<<g2, W2>>>(conv2_w, conv2_b);
    dim3 g3(NB, K3_CHUNKS);
    netvlad_fused_kernel<<<g3, K3A_THREADS>>>(aw, ab, cent, lw, lb, out);
}

// round 8
// speedup vs baseline: 1.2280x; 1.0213x over previous
#include <cuda_runtime.h>
#include <cstdint>

// Problem dims (fixed by reference)
#define NB   32
#define H0   512
#define W0   512
#define H1   256
#define W1   256
#define H2   128
#define W2   128
#define MPIX (H2*W2)   // 16384
#define K3_CHUNKS 8

// Scratch (device globals: allocation-free)
__device__ float g_h1[(size_t)NB * H1 * W1 * 4];   // NHWC (4ch per pixel)
__device__ float g_h2[(size_t)NB * MPIX * 16];     // NHWC pixel-major
__device__ float g_part[NB][K3_CHUNKS][68];        // netvlad partials
__device__ int   g_done[NB];                        // zero-init; self-resetting

// ---------------------------------------------------------------------------
// Kernel 1: conv1(3->4, 3x3 SAME) + ReLU + 2x2 avgpool, NCHW -> NHWC.
// Smem-staged; 2 pooled outputs per thread; vector LDS (conflict-free).
// grid = (H1, NB), block = 128
// ---------------------------------------------------------------------------
#define C1_THREADS 128
__global__ void __launch_bounds__(C1_THREADS) conv1_pool_kernel(
    const float* __restrict__ x,
    const float* __restrict__ w,   // (4,3,3,3)
    const float* __restrict__ b)
{
    __shared__ float  s_in[3][4][516];   // [ci][row][1+col]; halo cols 0 & 513 = 0
    __shared__ float4 sw4[27];
    __shared__ float  sb[4];
    const int tid = threadIdx.x;
    if (tid < 27)
        sw4[tid] = make_float4(w[tid], w[27 + tid], w[54 + tid], w[81 + tid]);
    if (tid < 4) sb[tid] = b[tid];

    const int py = blockIdx.x;
    const int n  = blockIdx.y;
    const int y0 = 2 * py - 1;

    if (tid < 12) {
        const int c = tid >> 2, r = tid & 3;
        s_in[c][r][0]   = 0.0f;
        s_in[c][r][513] = 0.0f;
        s_in[c][r][514] = 0.0f;
        s_in[c][r][515] = 0.0f;
    }

    // cooperative staging: 3*4*512 = 6144 scalars, 48 per thread, coalesced
    const float* xn = x + (size_t)n * 3 * H0 * W0;
#pragma unroll
    for (int i = 0; i < 48; ++i) {
        const int idx = tid + i * C1_THREADS;   // c*2048 + r*512 + col
        const int col = idx & 511;
        const int r   = (idx >> 9) & 3;
        const int c   = idx >> 11;
        const int y   = y0 + r;
        const float v = ((unsigned)y < (unsigned)H0)
                            ? __ldg(xn + (size_t)c * H0 * W0 + (size_t)y * W0 + col)
                            : 0.0f;
        s_in[c][r][1 + col] = v;
    }
    __syncthreads();

    // thread t: pooled outputs px0 = 2t, px1 = 2t+1
    // s_in index j in [4t, 4t+5] <-> conv col (4t-1)+j-4t = col base 4t-1
    float a00[4], a01[4], a10[4], a11[4];   // output 0
    float b00[4], b01[4], b10[4], b11[4];   // output 1
#pragma unroll
    for (int co = 0; co < 4; ++co) {
        const float bb = sb[co];
        a00[co] = bb; a01[co] = bb; a10[co] = bb; a11[co] = bb;
        b00[co] = bb; b01[co] = bb; b10[co] = bb; b11[co] = bb;
    }

    const int base = 4 * tid;
#pragma unroll
    for (int c = 0; c < 3; ++c) {
        float p[4][6];
#pragma unroll
        for (int dy = 0; dy < 4; ++dy) {
            const float4 q  = *(const float4*)&s_in[c][dy][base];
            const float2 q2 = *(const float2*)&s_in[c][dy][base + 4];
            p[dy][0] = q.x;  p[dy][1] = q.y;  p[dy][2] = q.z;
            p[dy][3] = q.w;  p[dy][4] = q2.x; p[dy][5] = q2.y;
        }
#pragma unroll
        for (int ky = 0; ky < 3; ++ky)
#pragma unroll
            for (int kx = 0; kx < 3; ++kx) {
                const float4 w4 = sw4[c * 9 + ky * 3 + kx];
                const float t00 = p[ky    ][kx    ];
                const float t01 = p[ky    ][kx + 1];
                const float t10 = p[ky + 1][kx    ];
                const float t11 = p[ky + 1][kx + 1];
                const float u00 = p[ky    ][kx + 2];
                const float u01 = p[ky    ][kx + 3];
                const float u10 = p[ky + 1][kx + 2];
                const float u11 = p[ky + 1][kx + 3];
                a00[0] = fmaf(t00, w4.x, a00[0]); a00[1] = fmaf(t00, w4.y, a00[1]);
                a00[2] = fmaf(t00, w4.z, a00[2]); a00[3] = fmaf(t00, w4.w, a00[3]);
                a01[0] = fmaf(t01, w4.x, a01[0]); a01[1] = fmaf(t01, w4.y, a01[1]);
                a01[2] = fmaf(t01, w4.z, a01[2]); a01[3] = fmaf(t01, w4.w, a01[3]);
                a10[0] = fmaf(t10, w4.x, a10[0]); a10[1] = fmaf(t10, w4.y, a10[1]);
                a10[2] = fmaf(t10, w4.z, a10[2]); a10[3] = fmaf(t10, w4.w, a10[3]);
                a11[0] = fmaf(t11, w4.x, a11[0]); a11[1] = fmaf(t11, w4.y, a11[1]);
                a11[2] = fmaf(t11, w4.z, a11[2]); a11[3] = fmaf(t11, w4.w, a11[3]);
                b00[0] = fmaf(u00, w4.x, b00[0]); b00[1] = fmaf(u00, w4.y, b00[1]);
                b00[2] = fmaf(u00, w4.z, b00[2]); b00[3] = fmaf(u00, w4.w, b00[3]);
                b01[0] = fmaf(u01, w4.x, b01[0]); b01[1] = fmaf(u01, w4.y, b01[1]);
                b01[2] = fmaf(u01, w4.z, b01[2]); b01[3] = fmaf(u01, w4.w, b01[3]);
                b10[0] = fmaf(u10, w4.x, b10[0]); b10[1] = fmaf(u10, w4.y, b10[1]);
                b10[2] = fmaf(u10, w4.z, b10[2]); b10[3] = fmaf(u10, w4.w, b10[3]);
                b11[0] = fmaf(u11, w4.x, b11[0]); b11[1] = fmaf(u11, w4.y, b11[1]);
                b11[2] = fmaf(u11, w4.z, b11[2]); b11[3] = fmaf(u11, w4.w, b11[3]);
            }
    }

    float r0[4], r1[4];
#pragma unroll
    for (int co = 0; co < 4; ++co) {
        r0[co] = 0.25f * (fmaxf(a00[co], 0.f) + fmaxf(a01[co], 0.f) +
                          fmaxf(a10[co], 0.f) + fmaxf(a11[co], 0.f));
        r1[co] = 0.25f * (fmaxf(b00[co], 0.f) + fmaxf(b01[co], 0.f) +
                          fmaxf(b10[co], 0.f) + fmaxf(b11[co], 0.f));
    }
    float4* o = (float4*)(g_h1 + (((size_t)n * H1 + py) * W1 + 2 * tid) * 4);
    o[0] = make_float4(r0[0], r0[1], r0[2], r0[3]);
    o[1] = make_float4(r1[0], r1[1], r1[2], r1[3]);
}

// ---------------------------------------------------------------------------
// Kernel 2: conv2(4->16, 3x3 SAME) + ReLU + 2x2 avgpool, NHWC -> NHWC (scalar,
// proven R3 version). grid = (H2, NB), block = 128
// ---------------------------------------------------------------------------
__global__ void __launch_bounds__(W2) conv2_pool_kernel(
    const float* __restrict__ w,   // (16,4,3,3)
    const float* __restrict__ b)
{
    __shared__ float4 sw4[4][36];
    __shared__ float  sb[16];
    const int tid = threadIdx.x;
    for (int i = tid; i < 144; i += W2) {
        const int g = i / 36, idx = i % 36;
        sw4[g][idx] = make_float4(w[(g * 4 + 0) * 36 + idx], w[(g * 4 + 1) * 36 + idx],
                                  w[(g * 4 + 2) * 36 + idx], w[(g * 4 + 3) * 36 + idx]);
    }
    if (tid < 16) sb[tid] = b[tid];
    __syncthreads();

    const int px = tid;
    const int py = blockIdx.x;
    const int n  = blockIdx.y;
    const int y0 = 2 * py - 1;
    const int x0 = 2 * px - 1;

    float p[4][4][4];
    const bool interior = (px >= 1) & (px <= 126) & (py >= 1) & (py <= 126);
    if (interior) {
        const float* bp = g_h1 + ((size_t)n * H1 * W1 + (size_t)y0 * W1 + x0) * 4;
#pragma unroll
        for (int dy = 0; dy < 4; ++dy)
#pragma unroll
            for (int dx = 0; dx < 4; ++dx) {
                const float4 t = *(const float4*)(bp + (dy * W1 + dx) * 4);
                p[dy][dx][0] = t.x; p[dy][dx][1] = t.y;
                p[dy][dx][2] = t.z; p[dy][dx][3] = t.w;
            }
    } else {
        const float* hn = g_h1 + (size_t)n * H1 * W1 * 4;
#pragma unroll
        for (int dy = 0; dy < 4; ++dy) {
            const int y = y0 + dy;
            const bool yok = ((unsigned)y < (unsigned)H1);
#pragma unroll
            for (int dx = 0; dx < 4; ++dx) {
                const int xx = x0 + dx;
                float4 t = make_float4(0.f, 0.f, 0.f, 0.f);
                if (yok && (unsigned)xx < (unsigned)W1)
                    t = *(const float4*)(hn + ((size_t)y * W1 + xx) * 4);
                p[dy][dx][0] = t.x; p[dy][dx][1] = t.y;
                p[dy][dx][2] = t.z; p[dy][dx][3] = t.w;
            }
        }
    }

    float res[16];
#pragma unroll
    for (int g = 0; g < 4; ++g) {
        float a00[4], a01[4], a10[4], a11[4];
#pragma unroll
        for (int j = 0; j < 4; ++j) {
            const float bb = sb[g * 4 + j];
            a00[j] = bb; a01[j] = bb; a10[j] = bb; a11[j] = bb;
        }
#pragma unroll
        for (int ci = 0; ci < 4; ++ci)
#pragma unroll
            for (int ky = 0; ky < 3; ++ky)
#pragma unroll
                for (int kx = 0; kx < 3; ++kx) {
                    const float4 w4 = sw4[g][(ci * 3 + ky) * 3 + kx];
                    const float t00 = p[ky    ][kx    ][ci];
                    const float t01 = p[ky    ][kx + 1][ci];
                    const float t10 = p[ky + 1][kx    ][ci];
                    const float t11 = p[ky + 1][kx + 1][ci];
                    a00[0] = fmaf(t00, w4.x, a00[0]); a00[1] = fmaf(t00, w4.y, a00[1]);
                    a00[2] = fmaf(t00, w4.z, a00[2]); a00[3] = fmaf(t00, w4.w, a00[3]);
                    a01[0] = fmaf(t01, w4.x, a01[0]); a01[1] = fmaf(t01, w4.y, a01[1]);
                    a01[2] = fmaf(t01, w4.z, a01[2]); a01[3] = fmaf(t01, w4.w, a01[3]);
                    a10[0] = fmaf(t10, w4.x, a10[0]); a10[1] = fmaf(t10, w4.y, a10[1]);
                    a10[2] = fmaf(t10, w4.z, a10[2]); a10[3] = fmaf(t10, w4.w, a10[3]);
                    a11[0] = fmaf(t11, w4.x, a11[0]); a11[1] = fmaf(t11, w4.y, a11[1]);
                    a11[2] = fmaf(t11, w4.z, a11[2]); a11[3] = fmaf(t11, w4.w, a11[3]);
                }
#pragma unroll
        for (int j = 0; j < 4; ++j)
            res[g * 4 + j] = 0.25f * (fmaxf(a00[j], 0.f) + fmaxf(a01[j], 0.f) +
                                      fmaxf(a10[j], 0.f) + fmaxf(a11[j], 0.f));
    }

    float4* o4 = (float4*)(g_h2 + ((size_t)n * MPIX + (size_t)py * W2 + px) * 16);
#pragma unroll
    for (int q = 0; q < 4; ++q)
        o4[q] = make_float4(res[q*4+0], res[q*4+1], res[q*4+2], res[q*4+3]);
}

// ---------------------------------------------------------------------------
// Kernel 3: NetVLAD partials + last-block finalize. grid=(NB, K3_CHUNKS), 256t
// ---------------------------------------------------------------------------
#define K3A_THREADS 256
__global__ void __launch_bounds__(K3A_THREADS) netvlad_fused_kernel(
    const float* __restrict__ aw, const float* __restrict__ ab,
    const float* __restrict__ cent,
    const float* __restrict__ lw, const float* __restrict__ lb,
    float* __restrict__ out)
{
    const int n   = blockIdx.x;
    const int ch  = blockIdx.y;
    const int tid = threadIdx.x;
    const int lane = tid & 31;
    const int wrp  = tid >> 5;

    __shared__ float s_aw[64];
    __shared__ float s_ab[4];
    if (tid < 64) s_aw[tid] = aw[tid];
    if (tid < 4)  s_ab[tid] = ab[tid];
    __syncthreads();

    float acc[68];
#pragma unroll
    for (int i = 0; i < 68; ++i) acc[i] = 0.0f;

    const int m0 = ch * (MPIX / K3_CHUNKS);
    const int m1 = m0 + (MPIX / K3_CHUNKS);
    const float* base = g_h2 + (size_t)n * MPIX * 16;
    for (int m = m0 + tid; m < m1; m += K3A_THREADS) {
        const float4* xp = (const float4*)(base + (size_t)m * 16);
        float xv[16];
#pragma unroll
        for (int q = 0; q < 4; ++q) {
            float4 v = xp[q];
            xv[q*4+0] = v.x; xv[q*4+1] = v.y; xv[q*4+2] = v.z; xv[q*4+3] = v.w;
        }
        float lg[4];
#pragma unroll
        for (int k = 0; k < 4; ++k) {
            float sres = s_ab[k];
#pragma unroll
            for (int c = 0; c < 16; ++c) sres = fmaf(xv[c], s_aw[k * 16 + c], sres);
            lg[k] = sres;
        }
        const float mx = fmaxf(fmaxf(lg[0], lg[1]), fmaxf(lg[2], lg[3]));
        float e[4], es = 0.0f;
#pragma unroll
        for (int k = 0; k < 4; ++k) { e[k] = __expf(lg[k] - mx); es += e[k]; }
        const float inv = __fdividef(1.0f, es);
#pragma unroll
        for (int k = 0; k < 4; ++k) {
            const float a = e[k] * inv;
            acc[64 + k] += a;
#pragma unroll
            for (int c = 0; c < 16; ++c)
                acc[k * 16 + c] = fmaf(a, xv[c], acc[k * 16 + c]);
        }
    }

#pragma unroll
    for (int off = 16; off > 0; off >>= 1)
#pragma unroll
        for (int i = 0; i < 68; ++i)
            acc[i] += __shfl_down_sync(0xffffffffu, acc[i], off);

    __shared__ float red[K3A_THREADS / 32][68];
    if (lane == 0)
#pragma unroll
        for (int i = 0; i < 68; ++i) red[wrp][i] = acc[i];
    __syncthreads();
    if (tid < 68) {
        float sres = 0.0f;
#pragma unroll
        for (int ww = 0; ww < K3A_THREADS / 32; ++ww) sres += red[ww][tid];
        g_part[n][ch][tid] = sres;
    }

    // ---- last-block-per-image finalize ----
    __threadfence();
    __shared__ int s_last;
    if (tid == 0) {
        const int old = atomicAdd(&g_done[n], 1);
        s_last = (old == K3_CHUNKS - 1) ? 1 : 0;
    }
    __syncthreads();
    if (!s_last) return;

    __shared__ float sv[68];
    if (tid < 68) {
        float sres = 0.0f;
#pragma unroll
        for (int cc = 0; cc < K3_CHUNKS; ++cc) sres += __ldcg(&g_part[n][cc][tid]);
        sv[tid] = sres;
    }
    __syncthreads();

    __shared__ float v2[64];
    __shared__ float nk[4];
    __shared__ float gn;
    if (tid < 64) {
        const int k = tid >> 4;
        v2[tid] = sv[tid] - sv[64 + k] * __ldg(cent + tid);
    }
    __syncthreads();
    if (tid < 4) {
        float sres = 0.0f;
#pragma unroll
        for (int c = 0; c < 16; ++c) { const float v = v2[tid * 16 + c]; sres = fmaf(v, v, sres); }
        nk[tid] = fmaxf(sqrtf(sres), 1e-12f);
    }
    __syncthreads();
    if (tid < 64) v2[tid] = v2[tid] / nk[tid >> 4];
    __syncthreads();
    if (tid == 0) {
        float sres = 0.0f;
#pragma unroll
        for (int i = 0; i < 64; ++i) sres = fmaf(v2[i], v2[i], sres);
        gn = fmaxf(sqrtf(sres), 1e-12f);
        g_done[n] = 0;   // reset for next graph replay
    }
    __syncthreads();
    if (tid < 7) {
        float sres = __ldg(lb + tid);
        const float ig = 1.0f / gn;
#pragma unroll
        for (int i = 0; i < 64; ++i)
            sres = fmaf(v2[i] * ig, __ldg(lw + tid * 64 + i), sres);
        out[n * 7 + tid] = sres;
    }
}

// ---------------------------------------------------------------------------
extern "C" void kernel_launch(void* const* d_in, const int* in_sizes, int n_in,
                              void* d_out, int out_size)
{
    (void)in_sizes; (void)n_in; (void)out_size;
    const float* x       = (const float*)d_in[0];
    const float* conv1_w = (const float*)d_in[1];
    const float* conv1_b = (const float*)d_in[2];
    const float* conv2_w = (const float*)d_in[3];
    const float* conv2_b = (const float*)d_in[4];
    const float* cent    = (const float*)d_in[5];
    const float* aw      = (const float*)d_in[6];
    const float* ab      = (const float*)d_in[7];
    const float* lw      = (const float*)d_in[8];
    const float* lb      = (const float*)d_in[9];
    float* out = (float*)d_out;

    dim3 g1(H1, NB); conv1_pool_kernel<<<g1, C1_THREADS>>>(x, conv1_w, conv1_b);
    dim3 g2(H2, NB); conv2_pool_kernel<<<g2, W2>>>(conv2_w, conv2_b);
    dim3 g3(NB, K3_CHUNKS);
    netvlad_fused_kernel<<<g3, K3A_THREADS>>>(aw, ab, cent, lw, lb, out);
}